// round 7
// baseline (speedup 1.0000x reference)
#include <cuda_runtime.h>

// Reference collapse (verified R1-R5, rel_err == 0.0 every round):
//   softmax over PRED_BITS == 1 axis => preds == 1.0 exactly; conv/FC dead code.
//   tuple_state sorted into segments b = 0..31; within_idx enumerates 0..n_b^2-1,
//   so at a segment end t: cnt_b = within_idx[t] + 1.
//   out[b, j] = (j < cnt_b), identical across all 3 branches.
//
// R6: the remaining cost is STORE ISSUE (1536 STG.128 ~ 4600 cyc on one SM's
// LSU path). Split stores across 4 CTAs: each block redundantly computes the
// 32 segment counts (loads are L2-shared), then writes a disjoint quarter of
// the output — exactly one STG.128 per thread for 384 threads.

#define BSZ   32
#define NTHR  1024
#define NBLK  4
#define F4TOT 1536   // 3 branches * 512 float4

__global__ __launch_bounds__(NTHR, 1)
void fosae_prefix_ones6(const int* __restrict__ ts,
                        const int* __restrict__ wi,
                        int T, int T4,
                        float4* __restrict__ out4)
{
    __shared__ int scnt[BSZ];

    const int tid = threadIdx.x;

    // ---- Boundary scan (all blocks do this; one int4 per thread).
    int4 v, w;
    int  nx = 0;
    bool full = false, tail = false;
    if (tid < T4) {
        const int t0 = tid << 2;
        if (t0 + 3 < T) {
            full = true;
            v  = ((const int4*)ts)[tid];
            w  = ((const int4*)wi)[tid];
            nx = (t0 + 4 < T) ? ts[t0 + 4] : -1;
        } else {
            tail = true;   // last partial vector, scalar fallback
        }
    }

    if (full) {
        if (v.x != v.y) scnt[v.x] = w.x + 1;
        if (v.y != v.z) scnt[v.y] = w.y + 1;
        if (v.z != v.w) scnt[v.z] = w.z + 1;
        if (v.w != nx)  scnt[v.w] = w.w + 1;
    } else if (tail) {
        for (int t = tid << 2; t < T; ++t) {
            const int b = ts[t];
            const int n = (t + 1 < T) ? ts[t + 1] : -1;
            if (b != n) scnt[b] = wi[t] + 1;
        }
    }
    __syncthreads();

    // ---- Each block writes its disjoint quarter: one STG.128 per thread.
    // Global float4 index g in [0, 1536); branch = g/512, b = (g%512)>>4,
    // j0 = 4*((g%512)&15).
    if (tid < F4TOT / NBLK) {
        const int g   = blockIdx.x * (F4TOT / NBLK) + tid;
        const int r   = g & 511;            // index within branch
        const int b   = r >> 4;
        const int j0  = (r & 15) << 2;
        const int cnt = scnt[b];
        float4 o;
        o.x = (j0 + 0 < cnt) ? 1.0f : 0.0f;
        o.y = (j0 + 1 < cnt) ? 1.0f : 0.0f;
        o.z = (j0 + 2 < cnt) ? 1.0f : 0.0f;
        o.w = (j0 + 3 < cnt) ? 1.0f : 0.0f;
        out4[g] = o;
    }
}

extern "C" void kernel_launch(void* const* d_in, const int* in_sizes, int n_in,
                              void* d_out, int out_size)
{
    const int* tuple_state = (const int*)d_in[12];
    const int* within_idx  = (const int*)d_in[15];
    const int  T           = in_sizes[12];
    const int  T4          = (T + 3) >> 2;

    fosae_prefix_ones6<<<NBLK, NTHR>>>(tuple_state, within_idx, T, T4,
                                       (float4*)d_out);
}